// round 9
// baseline (speedup 1.0000x reference)
#include <cuda_runtime.h>
#include <cuda_bf16.h>
#include <math.h>
#include <stdint.h>

#define NN 50000
#define NNP 50048          // NN padded to multiple of 128 (GEMM tile)
#define NE 800000
#define FIN 128
#define D1 256
#define D2 128
#define KC 32

// ---------------- scratch (device globals) ----------------
__device__ __align__(16) unsigned g_Ahi[(size_t)NNP * 64]; // bf16x2 (k-pairs) hi of aggX
__device__ __align__(16) unsigned g_Alo[(size_t)NNP * 64]; // lo
__device__ __align__(16) unsigned g_BThi[D2 * 64];         // Wc^T as bf16x2 k-pairs [n][kp]
__device__ __align__(16) unsigned g_BTlo[D2 * 64];
__device__ __align__(16) float g_abs[(size_t)NN * D2];     // tanh(aggX@Wc+bc)
__device__ __align__(16) float g_S[(size_t)NN * KC];       // softmax assign
__device__ __align__(16) float g_V[(size_t)NN * KC];       // S - W^T S (for adj)
__device__ float g_bc[D2];                                 // b1 @ fc1W + fc1b
__device__ float g_cs[FIN];                                // colsum(aggX)
__device__ int   g_deg_in[NN], g_deg_out[NN];
__device__ int   g_off_in[NN + 1];
__device__ int   g_cur_in[NN];
__device__ int   g_src_in[NE];             // CSR by target: source ids
__device__ float g_dinv1[NN], g_dinv2[NN];
__device__ float g_adj[KC * KC];

// ---------------- mma.sync bf16 (plain sm_80+ PTX; survives sm_103 target) ----------------
__device__ __forceinline__ void mma_bf16(float* d, unsigned a0, unsigned a1, unsigned b0) {
    asm volatile(
        "mma.sync.aligned.m16n8k8.row.col.f32.bf16.bf16.f32 "
        "{%0,%1,%2,%3}, {%4,%5}, {%6}, {%0,%1,%2,%3};"
        : "+f"(d[0]), "+f"(d[1]), "+f"(d[2]), "+f"(d[3])
        : "r"(a0), "r"(a1), "r"(b0));
}
__device__ __forceinline__ unsigned pack2bf(float a, float b) {
    unsigned ra = (unsigned)__bfloat16_as_ushort(__float2bfloat16(a));
    unsigned rb = (unsigned)__bfloat16_as_ushort(__float2bfloat16(b));
    return ra | (rb << 16);
}

// ---------------- init ----------------
__global__ void k_zero() {
    int i = blockIdx.x * blockDim.x + threadIdx.x;
    int stride = gridDim.x * blockDim.x;
    for (int j = i; j < NN; j += stride) {
        g_deg_in[j] = 0; g_deg_out[j] = 0; g_cur_in[j] = 0;
    }
    if (i < KC * KC) g_adj[i] = 0.f;
    if (i < FIN) g_cs[i] = 0.f;
}

__global__ void k_degree(const int* __restrict__ e) {
    int i = blockIdx.x * blockDim.x + threadIdx.x;
    int stride = gridDim.x * blockDim.x;
    for (int j = i; j < NE; j += stride) {
        atomicAdd(&g_deg_out[e[j]], 1);
        atomicAdd(&g_deg_in[e[NE + j]], 1);
    }
}

// block 0: scan deg_in -> off_in, emit dinv1.  block 1: dinv2 from deg_out (no scan needed).
__global__ __launch_bounds__(1024) void k_scan2() {
    int t = threadIdx.x;
    if (blockIdx.x == 1) {
        for (int idx = t; idx < NN; idx += 1024) {
            int v = g_deg_out[idx];
            g_dinv2[idx] = (v > 0) ? rsqrtf((float)v) : 0.f;
        }
        return;
    }
    __shared__ int wsum[32];
    __shared__ int carry;
    int lane = t & 31, w = t >> 5;
    if (t == 0) carry = 0;
    __syncthreads();
    for (int base = 0; base < NN; base += 1024) {
        int idx = base + t;
        int v = (idx < NN) ? g_deg_in[idx] : 0;
        if (idx < NN) g_dinv1[idx] = rsqrtf((float)(v + 1));
        int x = v;
        #pragma unroll
        for (int o = 1; o < 32; o <<= 1) {
            int y = __shfl_up_sync(0xffffffffu, x, o);
            if (lane >= o) x += y;
        }
        if (lane == 31) wsum[w] = x;
        __syncthreads();
        if (w == 0) {
            int s = wsum[lane];
            #pragma unroll
            for (int o = 1; o < 32; o <<= 1) {
                int y = __shfl_up_sync(0xffffffffu, s, o);
                if (lane >= o) s += y;
            }
            wsum[lane] = s;
        }
        __syncthreads();
        int incl = x + (w ? wsum[w - 1] : 0);
        if (idx < NN) g_off_in[idx] = carry + incl - v;
        int total = wsum[31];
        __syncthreads();
        if (t == 0) carry += total;
        __syncthreads();
    }
    if (t == 0) g_off_in[NN] = carry;
}

// fill in-CSR only
__global__ void k_fill(const int* __restrict__ e) {
    int i = blockIdx.x * blockDim.x + threadIdx.x;
    int stride = gridDim.x * blockDim.x;
    for (int j = i; j < NE; j += stride) {
        int r = e[j];
        int c = e[NE + j];
        int p = atomicAdd(&g_cur_in[c], 1);
        g_src_in[g_off_in[c] + p] = r;
    }
}

// ---------------- feature aggregation -> bf16 hi/lo + fused column sum ----------------
__global__ __launch_bounds__(256) void k_agg(const float* __restrict__ X) {
    __shared__ float cs[8][FIN];
    int w = threadIdx.x >> 5;
    int lane = threadIdx.x & 31;
    int i = blockIdx.x * 8 + w;
    float v[4] = {0.f, 0.f, 0.f, 0.f};
    if (i < NN) {
        float di = g_dinv1[i];
        const float4* X4 = (const float4*)X;
        float4 x = X4[(size_t)i * 32 + lane];
        float4 acc = make_float4(di * x.x, di * x.y, di * x.z, di * x.w);
        int s0 = g_off_in[i], s1 = g_off_in[i + 1];
        for (int idx = s0; idx < s1; idx++) {
            int s = g_src_in[idx];
            float ds = g_dinv1[s];
            float4 xs = X4[(size_t)s * 32 + lane];
            acc.x += ds * xs.x; acc.y += ds * xs.y;
            acc.z += ds * xs.z; acc.w += ds * xs.w;
        }
        v[0] = di * acc.x; v[1] = di * acc.y; v[2] = di * acc.z; v[3] = di * acc.w;
        float h[4], l[4];
        #pragma unroll
        for (int c = 0; c < 4; c++) {
            h[c] = __bfloat162float(__float2bfloat16(v[c]));
            l[c] = v[c] - h[c];
        }
        g_Ahi[(size_t)i * 64 + lane * 2 + 0] = pack2bf(h[0], h[1]);
        g_Ahi[(size_t)i * 64 + lane * 2 + 1] = pack2bf(h[2], h[3]);
        g_Alo[(size_t)i * 64 + lane * 2 + 0] = pack2bf(l[0], l[1]);
        g_Alo[(size_t)i * 64 + lane * 2 + 1] = pack2bf(l[2], l[3]);
    }
    *(float4*)&cs[w][lane * 4] = make_float4(v[0], v[1], v[2], v[3]);
    __syncthreads();
    if (threadIdx.x < FIN) {
        float s = 0.f;
        #pragma unroll
        for (int w2 = 0; w2 < 8; w2++) s += cs[w2][threadIdx.x];
        atomicAdd(&g_cs[threadIdx.x], s);
    }
}

// zero the pad rows of Ahi/Alo (rows NN..NNP)
__global__ void k_padzero() {
    int i = blockIdx.x * blockDim.x + threadIdx.x;
    int total = (NNP - NN) * 64;
    if (i < total) {
        g_Ahi[(size_t)NN * 64 + i] = 0;
        g_Alo[(size_t)NN * 64 + i] = 0;
    }
}

// ---------------- Wc = W1 @ fc1W, emitted as B^T bf16 hi/lo in [n][k-pair] layout ----------------
__global__ __launch_bounds__(128) void k_wc(
    const float* __restrict__ W1, const float* __restrict__ fc1W)
{
    __shared__ float w1s[8][16];
    int f0 = blockIdx.x * 16;
    int tid = threadIdx.x; // d2 column n
    float acc[16];
    #pragma unroll
    for (int f = 0; f < 16; f++) acc[f] = 0.f;
    for (int k0 = 0; k0 < D1; k0 += 8) {
        int kk = tid >> 4, ff = tid & 15;
        w1s[kk][ff] = W1[(size_t)(f0 + ff) * D1 + k0 + kk];
        __syncthreads();
        #pragma unroll
        for (int k = 0; k < 8; k++) {
            float b = fc1W[(size_t)(k0 + k) * D2 + tid];
            #pragma unroll
            for (int f = 0; f < 16; f++) acc[f] += w1s[k][f] * b;
        }
        __syncthreads();
    }
    #pragma unroll
    for (int f = 0; f < 16; f += 2) {
        float v0 = acc[f], v1 = acc[f + 1];
        float h0 = __bfloat162float(__float2bfloat16(v0));
        float h1 = __bfloat162float(__float2bfloat16(v1));
        int kp = (f0 + f) >> 1;
        g_BThi[tid * 64 + kp] = pack2bf(h0, h1);
        g_BTlo[tid * 64 + kp] = pack2bf(v0 - h0, v1 - h1);
    }
}

// bc = b1 @ fc1W + fc1b
__global__ __launch_bounds__(128) void k_bc(
    const float* __restrict__ b1, const float* __restrict__ fc1W,
    const float* __restrict__ fc1b)
{
    int t = threadIdx.x;
    float acc = fc1b[t];
    for (int k = 0; k < D1; k++) acc += b1[k] * fc1W[(size_t)k * D2 + t];
    g_bc[t] = acc;
}

// ---------------- HMMA GEMM: abs = tanh(aggX @ Wc + bc) ----------------
// CTA: 128 rows. 8 warps: warp_m = w>>1 (32 rows), warp_n = w&1 (64 cols).
// Per warp: 2 m16-tiles x 8 n8-tiles, K=128 in 16 chunks of 8, 3-term bf16 split.
__global__ __launch_bounds__(256) void k_gemm_mma() {
    int tid = threadIdx.x, w = tid >> 5, lane = tid & 31;
    int wm = w >> 1, wn = w & 1;
    int m_base = blockIdx.x * 128 + wm * 32;
    int n_base = wn * 64;
    int qr = lane >> 2, qc = lane & 3; // quad row / col

    float acc[2][8][4];
    #pragma unroll
    for (int mt = 0; mt < 2; mt++)
        #pragma unroll
        for (int nt = 0; nt < 8; nt++)
            #pragma unroll
            for (int f = 0; f < 4; f++) acc[mt][nt][f] = 0.f;

    #pragma unroll 4
    for (int kc = 0; kc < 16; kc++) {
        int kidx = kc * 4 + qc;
        unsigned ahi[2][2], alo[2][2];
        #pragma unroll
        for (int mt = 0; mt < 2; mt++) {
            size_t r = (size_t)(m_base + mt * 16 + qr);
            ahi[mt][0] = g_Ahi[r * 64 + kidx];
            ahi[mt][1] = g_Ahi[(r + 8) * 64 + kidx];
            alo[mt][0] = g_Alo[r * 64 + kidx];
            alo[mt][1] = g_Alo[(r + 8) * 64 + kidx];
        }
        #pragma unroll
        for (int nt = 0; nt < 8; nt++) {
            int ncol = n_base + nt * 8 + qr;
            unsigned bhi = g_BThi[ncol * 64 + kidx];
            unsigned blo = g_BTlo[ncol * 64 + kidx];
            #pragma unroll
            for (int mt = 0; mt < 2; mt++) {
                mma_bf16(acc[mt][nt], ahi[mt][0], ahi[mt][1], bhi);
                mma_bf16(acc[mt][nt], ahi[mt][0], ahi[mt][1], blo);
                mma_bf16(acc[mt][nt], alo[mt][0], alo[mt][1], bhi);
            }
        }
    }

    // epilogue: tanh(acc + bc), write float2 per fragment half
    #pragma unroll
    for (int nt = 0; nt < 8; nt++) {
        int c0 = n_base + nt * 8 + qc * 2;
        float b0 = g_bc[c0], b1 = g_bc[c0 + 1];
        #pragma unroll
        for (int mt = 0; mt < 2; mt++) {
            int r0 = m_base + mt * 16 + qr;
            if (r0 < NN) {
                float2 o = make_float2(tanhf(acc[mt][nt][0] + b0), tanhf(acc[mt][nt][1] + b1));
                *(float2*)&g_abs[(size_t)r0 * D2 + c0] = o;
            }
            if (r0 + 8 < NN) {
                float2 o = make_float2(tanhf(acc[mt][nt][2] + b0), tanhf(acc[mt][nt][3] + b1));
                *(float2*)&g_abs[(size_t)(r0 + 8) * D2 + c0] = o;
            }
        }
    }
}

// ---------------- fused fc2 + softmax ----------------
__global__ __launch_bounds__(256) void k_fc2_softmax(
    const float* __restrict__ W, const float* __restrict__ b)
{
    __shared__ float Ws[D2 * KC];
    __shared__ float bs[KC];
    int tid = threadIdx.x;
    for (int j = tid; j < D2 * KC; j += blockDim.x) Ws[j] = W[j];
    if (tid < KC) bs[tid] = b[tid];
    __syncthreads();
    int lane = tid & 31, warp = tid >> 5;
    int nwarps = (blockDim.x >> 5) * gridDim.x;
    for (int i = blockIdx.x * (blockDim.x >> 5) + warp; i < NN; i += nwarps) {
        float areg[4];
        #pragma unroll
        for (int j = 0; j < 4; j++) areg[j] = g_abs[(size_t)i * D2 + j * 32 + lane];
        float acc = bs[lane];
        #pragma unroll
        for (int j = 0; j < 4; j++)
            #pragma unroll
            for (int d = 0; d < 32; d++) {
                float a = __shfl_sync(0xffffffffu, areg[j], d);
                acc += a * Ws[(j * 32 + d) * KC + lane];
            }
        float m = acc;
        #pragma unroll
        for (int o = 16; o > 0; o >>= 1) m = fmaxf(m, __shfl_xor_sync(0xffffffffu, m, o));
        float e = expf(acc - m);
        float s = e;
        #pragma unroll
        for (int o = 16; o > 0; o >>= 1) s += __shfl_xor_sync(0xffffffffu, s, o);
        g_S[(size_t)i * KC + lane] = e / s;
    }
}

// ---------------- V[c] = S[c] - dinv2[c]*sum_{r in in(c)} dinv2[r]*S[r]  (in-CSR gather) ----------------
__global__ __launch_bounds__(256) void k_lapV() {
    int tid = blockIdx.x * blockDim.x + threadIdx.x;
    int lane = tid & 31;
    int i = tid >> 5;
    if (i >= NN) return;
    float sv = g_S[(size_t)i * KC + lane];
    float di = g_dinv2[i];
    float u = 0.f;
    int s0 = g_off_in[i], s1 = g_off_in[i + 1];
    for (int idx = s0; idx < s1; idx++) {
        int r = g_src_in[idx];
        u += g_dinv2[r] * g_S[(size_t)r * KC + lane];
    }
    g_V[(size_t)i * KC + lane] = sv - di * u;
}

// ---------------- adj[a][b] = sum_i V[i,a] * S[i,b] ----------------
__global__ __launch_bounds__(256) void k_adj() {
    __shared__ float sh[8][KC * KC];
    int tid = threadIdx.x, lane = tid & 31, w = tid >> 5;
    float acc[32];
    #pragma unroll
    for (int a = 0; a < 32; a++) acc[a] = 0.f;
    int gw = blockIdx.x * 8 + w, tw = gridDim.x * 8;
    for (int i = gw; i < NN; i += tw) {
        float vv = g_V[(size_t)i * 32 + lane];
        float sv = g_S[(size_t)i * 32 + lane];
        #pragma unroll
        for (int a = 0; a < 32; a++) {
            float va = __shfl_sync(0xffffffffu, vv, a);
            acc[a] += va * sv;
        }
    }
    #pragma unroll
    for (int a = 0; a < 32; a++) sh[w][a * 32 + lane] = acc[a];
    __syncthreads();
    for (int j = tid; j < KC * KC; j += blockDim.x) {
        float s = 0.f;
        #pragma unroll
        for (int w2 = 0; w2 < 8; w2++) s += sh[w2][j];
        atomicAdd(&g_adj[j], s);
    }
}

// ---------------- finalize: emb = (cs@W1 + NN*b1)/32 ; pos_penalty ----------------
__global__ void k_final(const float* __restrict__ W1, const float* __restrict__ b1,
                        float* __restrict__ out, int out_size) {
    int t = threadIdx.x; // 256 = D1
    float acc = (float)NN * b1[t];
    for (int f = 0; f < FIN; f++) acc += g_cs[f] * W1[(size_t)f * D1 + t];
    if (t < out_size) out[t] = acc * (1.f / 32.f);
    if (t < 32) {
        float rs = 0.f;
        #pragma unroll
        for (int b = 0; b < 32; b++) rs += fabsf(g_adj[t * 32 + b]);
        float d = g_adj[t * 33] / fmaxf(rs, 1e-12f);
        float contrib = (d - 1.f) * (d - 1.f) + 31.f * d * d;
        #pragma unroll
        for (int o = 16; o > 0; o >>= 1) contrib += __shfl_xor_sync(0xffffffffu, contrib, o);
        if (t == 0 && out_size > D1) out[D1] = contrib * (1.f / 1024.f);
    }
}

// ---------------- launch ----------------
extern "C" void kernel_launch(void* const* d_in, const int* in_sizes, int n_in,
                              void* d_out, int out_size) {
    const float* feat  = (const float*)d_in[0];
    const int*   edges = (const int*)d_in[1];   // (2, E) int32
    const float* W1    = (const float*)d_in[2];
    const float* b1    = (const float*)d_in[3];
    const float* fc1W  = (const float*)d_in[4];
    const float* fc1b  = (const float*)d_in[5];
    const float* fc2W  = (const float*)d_in[6];
    const float* fc2b  = (const float*)d_in[7];
    float* out = (float*)d_out;

    k_zero<<<256, 256>>>();
    k_degree<<<1024, 256>>>(edges);
    k_scan2<<<2, 1024>>>();
    k_fill<<<1024, 256>>>(edges);
    k_wc<<<8, 128>>>(W1, fc1W);
    k_bc<<<1, 128>>>(b1, fc1W, fc1b);
    k_padzero<<<((NNP - NN) * 64 + 255) / 256, 256>>>();
    k_agg<<<(NN + 7) / 8, 256>>>(feat);
    k_gemm_mma<<<NNP / 128, 256>>>();
    k_fc2_softmax<<<296, 256>>>(fc2W, fc2b);
    k_lapV<<<(NN * 32 + 255) / 256, 256>>>();
    k_adj<<<148, 256>>>();
    k_final<<<1, 256>>>(W1, b1, out, out_size);
}

// round 10
// speedup vs baseline: 1.2918x; 1.2918x over previous
#include <cuda_runtime.h>
#include <math.h>
#include <stdint.h>

#define NN 50000
#define NE 800000
#define FIN 128
#define D1 256
#define D2 128
#define KC 32

// ---------------- scratch (device globals) ----------------
__device__ __align__(16) float g_aggX[(size_t)NN * FIN];  // normalized (A+I) agg of features
__device__ __align__(16) float g_S[(size_t)NN * KC];      // softmax assign
__device__ __align__(16) float g_V[(size_t)NN * KC];      // S - W^T S (for adj)
__device__ __align__(16) float g_Wc[FIN * D2];            // W1 @ fc1W  (128x128) [k][n]
__device__ float g_bc[D2];                                 // b1 @ fc1W + fc1b
__device__ float g_cs[FIN];                                // colsum(aggX)
__device__ int   g_deg_in[NN], g_deg_out[NN];
__device__ int   g_off_in[NN + 1];
__device__ int   g_cur_in[NN];
__device__ int   g_src_in[NE];             // CSR by target: source ids
__device__ float g_dinv1[NN], g_dinv2[NN];
__device__ float g_adj[KC * KC];

// ---------------- init ----------------
__global__ void k_zero() {
    int i = blockIdx.x * blockDim.x + threadIdx.x;
    int stride = gridDim.x * blockDim.x;
    for (int j = i; j < NN; j += stride) {
        g_deg_in[j] = 0; g_deg_out[j] = 0; g_cur_in[j] = 0;
    }
    if (i < KC * KC) g_adj[i] = 0.f;
    if (i < FIN) g_cs[i] = 0.f;
}

__global__ void k_degree(const int* __restrict__ e) {
    int i = blockIdx.x * blockDim.x + threadIdx.x;
    int stride = gridDim.x * blockDim.x;
    for (int j = i; j < NE; j += stride) {
        atomicAdd(&g_deg_out[e[j]], 1);
        atomicAdd(&g_deg_in[e[NE + j]], 1);
    }
}

// block 0: scan deg_in -> off_in, emit dinv1.  block 1: dinv2 from deg_out.
__global__ __launch_bounds__(1024) void k_scan2() {
    int t = threadIdx.x;
    if (blockIdx.x == 1) {
        for (int idx = t; idx < NN; idx += 1024) {
            int v = g_deg_out[idx];
            g_dinv2[idx] = (v > 0) ? rsqrtf((float)v) : 0.f;
        }
        return;
    }
    __shared__ int wsum[32];
    __shared__ int carry;
    int lane = t & 31, w = t >> 5;
    if (t == 0) carry = 0;
    __syncthreads();
    for (int base = 0; base < NN; base += 1024) {
        int idx = base + t;
        int v = (idx < NN) ? g_deg_in[idx] : 0;
        if (idx < NN) g_dinv1[idx] = rsqrtf((float)(v + 1));
        int x = v;
        #pragma unroll
        for (int o = 1; o < 32; o <<= 1) {
            int y = __shfl_up_sync(0xffffffffu, x, o);
            if (lane >= o) x += y;
        }
        if (lane == 31) wsum[w] = x;
        __syncthreads();
        if (w == 0) {
            int s = wsum[lane];
            #pragma unroll
            for (int o = 1; o < 32; o <<= 1) {
                int y = __shfl_up_sync(0xffffffffu, s, o);
                if (lane >= o) s += y;
            }
            wsum[lane] = s;
        }
        __syncthreads();
        int incl = x + (w ? wsum[w - 1] : 0);
        if (idx < NN) g_off_in[idx] = carry + incl - v;
        int total = wsum[31];
        __syncthreads();
        if (t == 0) carry += total;
        __syncthreads();
    }
    if (t == 0) g_off_in[NN] = carry;
}

// fill in-CSR only
__global__ void k_fill(const int* __restrict__ e) {
    int i = blockIdx.x * blockDim.x + threadIdx.x;
    int stride = gridDim.x * blockDim.x;
    for (int j = i; j < NE; j += stride) {
        int r = e[j];
        int c = e[NE + j];
        int p = atomicAdd(&g_cur_in[c], 1);
        g_src_in[g_off_in[c] + p] = r;
    }
}

// ---------------- feature aggregation + fused column sum ----------------
__global__ __launch_bounds__(256) void k_agg(const float* __restrict__ X) {
    __shared__ float cs[8][FIN];
    int w = threadIdx.x >> 5;
    int lane = threadIdx.x & 31;
    int i = blockIdx.x * 8 + w;
    float4 o = make_float4(0.f, 0.f, 0.f, 0.f);
    if (i < NN) {
        float di = g_dinv1[i];
        const float4* X4 = (const float4*)X;
        float4 x = X4[(size_t)i * 32 + lane];
        float4 acc = make_float4(di * x.x, di * x.y, di * x.z, di * x.w);
        int s0 = g_off_in[i], s1 = g_off_in[i + 1];
        for (int idx = s0; idx < s1; idx++) {
            int s = g_src_in[idx];
            float ds = g_dinv1[s];
            float4 xs = X4[(size_t)s * 32 + lane];
            acc.x += ds * xs.x; acc.y += ds * xs.y;
            acc.z += ds * xs.z; acc.w += ds * xs.w;
        }
        o = make_float4(di * acc.x, di * acc.y, di * acc.z, di * acc.w);
        ((float4*)g_aggX)[(size_t)i * 32 + lane] = o;
    }
    *(float4*)&cs[w][lane * 4] = o;
    __syncthreads();
    if (threadIdx.x < FIN) {
        float s = 0.f;
        #pragma unroll
        for (int w2 = 0; w2 < 8; w2++) s += cs[w2][threadIdx.x];
        atomicAdd(&g_cs[threadIdx.x], s);
    }
}

// ---------------- Wc = W1 @ fc1W  (128x256 @ 256x128) ----------------
__global__ __launch_bounds__(128) void k_wc(
    const float* __restrict__ W1, const float* __restrict__ fc1W)
{
    __shared__ float w1s[8][16];
    int f0 = blockIdx.x * 16;
    int tid = threadIdx.x; // d2 column
    float acc[16];
    #pragma unroll
    for (int f = 0; f < 16; f++) acc[f] = 0.f;
    for (int k0 = 0; k0 < D1; k0 += 8) {
        int kk = tid >> 4, ff = tid & 15;
        w1s[kk][ff] = W1[(size_t)(f0 + ff) * D1 + k0 + kk];
        __syncthreads();
        #pragma unroll
        for (int k = 0; k < 8; k++) {
            float b = fc1W[(size_t)(k0 + k) * D2 + tid];
            #pragma unroll
            for (int f = 0; f < 16; f++) acc[f] += w1s[k][f] * b;
        }
        __syncthreads();
    }
    #pragma unroll
    for (int f = 0; f < 16; f++) g_Wc[(size_t)(f0 + f) * D2 + tid] = acc[f];
}

// bc = b1 @ fc1W + fc1b
__global__ __launch_bounds__(128) void k_bc(
    const float* __restrict__ b1, const float* __restrict__ fc1W,
    const float* __restrict__ fc1b)
{
    int t = threadIdx.x;
    float acc = fc1b[t];
    for (int k = 0; k < D1; k++) acc += b1[k] * fc1W[(size_t)k * D2 + t];
    g_bc[t] = acc;
}

// ---------------- fused GEMM + tanh + fc2 + softmax ----------------
// abs_row = tanh(aggX @ Wc + bc); S = softmax(abs_row @ fc2W + fc2b)
// 64x128 tile (full N), BK=8, 256 threads, 4x8 microtile; epilogue in 2 phases of 32 rows.
__global__ __launch_bounds__(256) void k_gemm_fused(
    const float* __restrict__ fc2W, const float* __restrict__ fc2b)
{
    const float* __restrict__ A = g_aggX;
    const float* __restrict__ B = g_Wc;
    __shared__ float As[8][64];
    __shared__ float Bs[8][128];
    __shared__ float abs_s[32][128]; // 16 KB, one phase of rows
    __shared__ float Ws[D2 * KC];    // 16 KB fc2 weights
    __shared__ float bs_s[KC];
    int tid = threadIdx.x;
    int m0 = blockIdx.x * 64;
    int tx = tid % 16, ty = tid / 16;

    for (int j = tid; j < D2 * KC; j += 256) Ws[j] = fc2W[j];
    if (tid < KC) bs_s[tid] = fc2b[tid];

    int ar = tid >> 2, ak = (tid & 3) * 2;   // A fill: row 0..63, k pair
    int bk = tid >> 5, bn = (tid & 31) * 4;  // B fill

    float acc[4][8];
    #pragma unroll
    for (int i = 0; i < 4; i++)
        #pragma unroll
        for (int j = 0; j < 8; j++) acc[i][j] = 0.f;

    for (int k0 = 0; k0 < FIN; k0 += 8) {
        float2 av = make_float2(0.f, 0.f);
        if (m0 + ar < NN) av = *(const float2*)&A[(size_t)(m0 + ar) * FIN + k0 + ak];
        As[ak + 0][ar] = av.x;
        As[ak + 1][ar] = av.y;
        float4 bv = *(const float4*)&B[(size_t)(k0 + bk) * D2 + bn];
        *(float4*)&Bs[bk][bn] = bv;
        __syncthreads();
        #pragma unroll
        for (int k = 0; k < 8; k++) {
            float4 a0 = *(const float4*)&As[k][ty * 4];
            float4 b0 = *(const float4*)&Bs[k][tx * 8];
            float4 b1 = *(const float4*)&Bs[k][tx * 8 + 4];
            float aR[4] = {a0.x, a0.y, a0.z, a0.w};
            float bR[8] = {b0.x, b0.y, b0.z, b0.w, b1.x, b1.y, b1.z, b1.w};
            #pragma unroll
            for (int i = 0; i < 4; i++)
                #pragma unroll
                for (int j = 0; j < 8; j++)
                    acc[i][j] += aR[i] * bR[j];
        }
        __syncthreads();
    }

    // bias + tanh into v
    float bloc[8];
    #pragma unroll
    for (int j = 0; j < 8; j++) bloc[j] = g_bc[tx * 8 + j];
    float v[4][8];
    #pragma unroll
    for (int i = 0; i < 4; i++)
        #pragma unroll
        for (int j = 0; j < 8; j++) v[i][j] = tanhf(acc[i][j] + bloc[j]);

    int w = tid >> 5, lane = tid & 31;
    #pragma unroll
    for (int ph = 0; ph < 2; ph++) {
        // stage this phase's 32 rows into smem
        if (ty >= ph * 8 && ty < ph * 8 + 8) {
            int lr = ty * 4 - ph * 32;
            #pragma unroll
            for (int i = 0; i < 4; i++)
                #pragma unroll
                for (int j = 0; j < 8; j++)
                    abs_s[lr + i][tx * 8 + j] = v[i][j];
        }
        __syncthreads();
        // fc2 + softmax: 8 warps x 4 rows
        #pragma unroll
        for (int rr = 0; rr < 4; rr++) {
            int lr = w * 4 + rr;
            int grow = m0 + ph * 32 + lr;
            float areg[4];
            #pragma unroll
            for (int j = 0; j < 4; j++) areg[j] = abs_s[lr][j * 32 + lane];
            float a2 = bs_s[lane];
            #pragma unroll
            for (int j = 0; j < 4; j++)
                #pragma unroll
                for (int d = 0; d < 32; d++) {
                    float a = __shfl_sync(0xffffffffu, areg[j], d);
                    a2 += a * Ws[(j * 32 + d) * KC + lane];
                }
            float m = a2;
            #pragma unroll
            for (int o = 16; o > 0; o >>= 1) m = fmaxf(m, __shfl_xor_sync(0xffffffffu, m, o));
            float e = expf(a2 - m);
            float s = e;
            #pragma unroll
            for (int o = 16; o > 0; o >>= 1) s += __shfl_xor_sync(0xffffffffu, s, o);
            if (grow < NN) g_S[(size_t)grow * KC + lane] = e / s;
        }
        __syncthreads();
    }
}

// ---------------- V[c] = S[c] - dinv2[c]*sum_{r in in(c)} dinv2[r]*S[r] ----------------
__global__ __launch_bounds__(256) void k_lapV() {
    int tid = blockIdx.x * blockDim.x + threadIdx.x;
    int lane = tid & 31;
    int i = tid >> 5;
    if (i >= NN) return;
    float sv = g_S[(size_t)i * KC + lane];
    float di = g_dinv2[i];
    float u = 0.f;
    int s0 = g_off_in[i], s1 = g_off_in[i + 1];
    for (int idx = s0; idx < s1; idx++) {
        int r = g_src_in[idx];
        u += g_dinv2[r] * g_S[(size_t)r * KC + lane];
    }
    g_V[(size_t)i * KC + lane] = sv - di * u;
}

// ---------------- adj[a][b] = sum_i V[i,a] * S[i,b] ----------------
__global__ __launch_bounds__(256) void k_adj() {
    __shared__ float sh[8][KC * KC];
    int tid = threadIdx.x, lane = tid & 31, w = tid >> 5;
    float acc[32];
    #pragma unroll
    for (int a = 0; a < 32; a++) acc[a] = 0.f;
    int gw = blockIdx.x * 8 + w, tw = gridDim.x * 8;
    for (int i = gw; i < NN; i += tw) {
        float vv = g_V[(size_t)i * 32 + lane];
        float sv = g_S[(size_t)i * 32 + lane];
        #pragma unroll
        for (int a = 0; a < 32; a++) {
            float va = __shfl_sync(0xffffffffu, vv, a);
            acc[a] += va * sv;
        }
    }
    #pragma unroll
    for (int a = 0; a < 32; a++) sh[w][a * 32 + lane] = acc[a];
    __syncthreads();
    for (int j = tid; j < KC * KC; j += blockDim.x) {
        float s = 0.f;
        #pragma unroll
        for (int w2 = 0; w2 < 8; w2++) s += sh[w2][j];
        atomicAdd(&g_adj[j], s);
    }
}

// ---------------- finalize: emb = (cs@W1 + NN*b1)/32 ; pos_penalty ----------------
__global__ void k_final(const float* __restrict__ W1, const float* __restrict__ b1,
                        float* __restrict__ out, int out_size) {
    int t = threadIdx.x; // 256 = D1
    float acc = (float)NN * b1[t];
    for (int f = 0; f < FIN; f++) acc += g_cs[f] * W1[(size_t)f * D1 + t];
    if (t < out_size) out[t] = acc * (1.f / 32.f);
    if (t < 32) {
        float rs = 0.f;
        #pragma unroll
        for (int b = 0; b < 32; b++) rs += fabsf(g_adj[t * 32 + b]);
        float d = g_adj[t * 33] / fmaxf(rs, 1e-12f);
        float contrib = (d - 1.f) * (d - 1.f) + 31.f * d * d;
        #pragma unroll
        for (int o = 16; o > 0; o >>= 1) contrib += __shfl_xor_sync(0xffffffffu, contrib, o);
        if (t == 0 && out_size > D1) out[D1] = contrib * (1.f / 1024.f);
    }
}

// ---------------- launch ----------------
extern "C" void kernel_launch(void* const* d_in, const int* in_sizes, int n_in,
                              void* d_out, int out_size) {
    const float* feat  = (const float*)d_in[0];
    const int*   edges = (const int*)d_in[1];   // (2, E) int32
    const float* W1    = (const float*)d_in[2];
    const float* b1    = (const float*)d_in[3];
    const float* fc1W  = (const float*)d_in[4];
    const float* fc1b  = (const float*)d_in[5];
    const float* fc2W  = (const float*)d_in[6];
    const float* fc2b  = (const float*)d_in[7];
    float* out = (float*)d_out;

    k_zero<<<256, 256>>>();
    k_degree<<<1024, 256>>>(edges);
    k_scan2<<<2, 1024>>>();
    k_fill<<<1024, 256>>>(edges);
    k_wc<<<8, 128>>>(W1, fc1W);
    k_bc<<<1, 128>>>(b1, fc1W, fc1b);
    k_agg<<<(NN + 7) / 8, 256>>>(feat);
    k_gemm_fused<<<(NN + 63) / 64, 256>>>(fc2W, fc2b);
    k_lapV<<<(NN * 32 + 255) / 256, 256>>>();
    k_adj<<<148, 256>>>();
    k_final<<<1, 256>>>(W1, b1, out, out_size);
}

// round 11
// speedup vs baseline: 1.4363x; 1.1119x over previous
#include <cuda_runtime.h>
#include <math.h>
#include <stdint.h>

#define NN 50000
#define NE 800000
#define FIN 128
#define D1 256
#define D2 128
#define KC 32

// ---------------- scratch (device globals) ----------------
__device__ __align__(16) float g_aggX[(size_t)NN * FIN];  // normalized (A+I) agg of features
__device__ __align__(16) float g_S[(size_t)NN * KC];      // softmax assign
__device__ __align__(16) float g_V[(size_t)NN * KC];      // S - W^T S (for adj)
__device__ __align__(16) float g_Wc[FIN * D2];            // W1 @ fc1W  (128x128) [k][n]
__device__ float g_bc[D2];                                 // b1 @ fc1W + fc1b
__device__ __align__(16) int g_deg[2 * NN];                // [0,NN): deg_in  [NN,2NN): deg_out
__device__ int   g_off_in[NN + 1];                         // exclusive offsets; post-fill = segment ENDs
__device__ int   g_src_in[NE];                             // CSR by target: source ids
__device__ float g_dinv1[NN], g_dinv2[NN];
__device__ __align__(16) float g_small[KC * KC + FIN];     // [0,1024): adj  [1024,1152): cs

#define G_ADJ(i) g_small[i]
#define G_CS(i)  g_small[KC * KC + (i)]

// ---------------- degree histogram ----------------
__global__ void k_degree(const int* __restrict__ e) {
    int i = blockIdx.x * blockDim.x + threadIdx.x;
    int stride = gridDim.x * blockDim.x;
    for (int j = i; j < NE; j += stride) {
        atomicAdd(&g_deg[NN + e[j]], 1);      // out-degree of source
        atomicAdd(&g_deg[e[NE + j]], 1);      // in-degree of target
    }
}

// block 0: scan deg_in -> off_in, emit dinv1.  block 1: dinv2 from deg_out.
__global__ __launch_bounds__(1024) void k_scan2() {
    int t = threadIdx.x;
    if (blockIdx.x == 1) {
        for (int idx = t; idx < NN; idx += 1024) {
            int v = g_deg[NN + idx];
            g_dinv2[idx] = (v > 0) ? rsqrtf((float)v) : 0.f;
        }
        return;
    }
    __shared__ int wsum[32];
    __shared__ int carry;
    int lane = t & 31, w = t >> 5;
    if (t == 0) carry = 0;
    __syncthreads();
    for (int base = 0; base < NN; base += 1024) {
        int idx = base + t;
        int v = (idx < NN) ? g_deg[idx] : 0;
        if (idx < NN) g_dinv1[idx] = rsqrtf((float)(v + 1));
        int x = v;
        #pragma unroll
        for (int o = 1; o < 32; o <<= 1) {
            int y = __shfl_up_sync(0xffffffffu, x, o);
            if (lane >= o) x += y;
        }
        if (lane == 31) wsum[w] = x;
        __syncthreads();
        if (w == 0) {
            int s = wsum[lane];
            #pragma unroll
            for (int o = 1; o < 32; o <<= 1) {
                int y = __shfl_up_sync(0xffffffffu, s, o);
                if (lane >= o) s += y;
            }
            wsum[lane] = s;
        }
        __syncthreads();
        int incl = x + (w ? wsum[w - 1] : 0);
        if (idx < NN) g_off_in[idx] = carry + incl - v;
        int total = wsum[31];
        __syncthreads();
        if (t == 0) carry += total;
        __syncthreads();
    }
}

// fill in-CSR; off_in doubles as cursor (post-fill off_in[c] = end of segment c)
__global__ void k_fill(const int* __restrict__ e) {
    int i = blockIdx.x * blockDim.x + threadIdx.x;
    int stride = gridDim.x * blockDim.x;
    for (int j = i; j < NE; j += stride) {
        int r = e[j];
        int c = e[NE + j];
        int p = atomicAdd(&g_off_in[c], 1);
        g_src_in[p] = r;
    }
}

// ---------------- feature aggregation + fused column sum ----------------
// segment of node i: [i ? off[i-1] : 0, off[i])  (post-fill ends)
__global__ __launch_bounds__(256) void k_agg(const float* __restrict__ X) {
    __shared__ float cs[8][FIN];
    int w = threadIdx.x >> 5;
    int lane = threadIdx.x & 31;
    int i = blockIdx.x * 8 + w;
    float4 o = make_float4(0.f, 0.f, 0.f, 0.f);
    if (i < NN) {
        float di = g_dinv1[i];
        const float4* X4 = (const float4*)X;
        float4 x = X4[(size_t)i * 32 + lane];
        float4 acc = make_float4(di * x.x, di * x.y, di * x.z, di * x.w);
        int s0 = i ? g_off_in[i - 1] : 0;
        int s1 = g_off_in[i];
        for (int idx = s0; idx < s1; idx++) {
            int s = g_src_in[idx];
            float ds = g_dinv1[s];
            float4 xs = X4[(size_t)s * 32 + lane];
            acc.x += ds * xs.x; acc.y += ds * xs.y;
            acc.z += ds * xs.z; acc.w += ds * xs.w;
        }
        o = make_float4(di * acc.x, di * acc.y, di * acc.z, di * acc.w);
        ((float4*)g_aggX)[(size_t)i * 32 + lane] = o;
    }
    *(float4*)&cs[w][lane * 4] = o;
    __syncthreads();
    if (threadIdx.x < FIN) {
        float s = 0.f;
        #pragma unroll
        for (int w2 = 0; w2 < 8; w2++) s += cs[w2][threadIdx.x];
        atomicAdd(&G_CS(threadIdx.x), s);
    }
}

// ---------------- Wc = W1 @ fc1W (blocks 0-7); bc = b1@fc1W + fc1b (block 8) ----------------
__global__ __launch_bounds__(128) void k_wcbc(
    const float* __restrict__ W1, const float* __restrict__ fc1W,
    const float* __restrict__ b1, const float* __restrict__ fc1b)
{
    int tid = threadIdx.x;
    if (blockIdx.x == 8) {
        float acc = fc1b[tid];
        for (int k = 0; k < D1; k++) acc += b1[k] * fc1W[(size_t)k * D2 + tid];
        g_bc[tid] = acc;
        return;
    }
    __shared__ float w1s[8][16];
    int f0 = blockIdx.x * 16;
    float acc[16];
    #pragma unroll
    for (int f = 0; f < 16; f++) acc[f] = 0.f;
    for (int k0 = 0; k0 < D1; k0 += 8) {
        int kk = tid >> 4, ff = tid & 15;
        w1s[kk][ff] = W1[(size_t)(f0 + ff) * D1 + k0 + kk];
        __syncthreads();
        #pragma unroll
        for (int k = 0; k < 8; k++) {
            float b = fc1W[(size_t)(k0 + k) * D2 + tid];
            #pragma unroll
            for (int f = 0; f < 16; f++) acc[f] += w1s[k][f] * b;
        }
        __syncthreads();
    }
    #pragma unroll
    for (int f = 0; f < 16; f++) g_Wc[(size_t)(f0 + f) * D2 + tid] = acc[f];
}

// ---------------- fused GEMM + tanh + fc2 + softmax ----------------
// 64x128 tile, BK=8, 256 threads, 4x8 microtile, register-pipelined loads.
// Epilogue: 8 phases of 8 rows staged over the DEAD mainloop smem (aliased).
__global__ __launch_bounds__(256) void k_gemm_fused(
    const float* __restrict__ fc2W, const float* __restrict__ fc2b)
{
    const float* __restrict__ A = g_aggX;
    const float* __restrict__ B = g_Wc;
    __shared__ __align__(16) float smem_main[8 * 64 + 8 * 128]; // As | Bs = 6 KB
    __shared__ float Ws[D2 * KC];    // 16 KB fc2 weights
    __shared__ float bs_s[KC];
    float (*As)[64]  = (float(*)[64])smem_main;
    float (*Bs)[128] = (float(*)[128])(smem_main + 8 * 64);
    int tid = threadIdx.x;
    int m0 = blockIdx.x * 64;
    int tx = tid % 16, ty = tid / 16;

    for (int j = tid; j < D2 * KC; j += 256) Ws[j] = fc2W[j];
    if (tid < KC) bs_s[tid] = fc2b[tid];

    int ar = tid >> 2, ak = (tid & 3) * 2;   // A fill: row 0..63, k pair
    int bk = tid >> 5, bn = (tid & 31) * 4;  // B fill

    float acc[4][8];
    #pragma unroll
    for (int i = 0; i < 4; i++)
        #pragma unroll
        for (int j = 0; j < 8; j++) acc[i][j] = 0.f;

    // register-pipelined mainloop
    float2 av = make_float2(0.f, 0.f);
    if (m0 + ar < NN) av = *(const float2*)&A[(size_t)(m0 + ar) * FIN + ak];
    float4 bv = *(const float4*)&B[(size_t)bk * D2 + bn];

    #pragma unroll 1
    for (int k0 = 0; k0 < FIN; k0 += 8) {
        As[ak + 0][ar] = av.x;
        As[ak + 1][ar] = av.y;
        *(float4*)&Bs[bk][bn] = bv;
        __syncthreads();
        if (k0 + 8 < FIN) {
            av = make_float2(0.f, 0.f);
            if (m0 + ar < NN) av = *(const float2*)&A[(size_t)(m0 + ar) * FIN + k0 + 8 + ak];
            bv = *(const float4*)&B[(size_t)(k0 + 8 + bk) * D2 + bn];
        }
        #pragma unroll
        for (int k = 0; k < 8; k++) {
            float4 a0 = *(const float4*)&As[k][ty * 4];
            float4 b0 = *(const float4*)&Bs[k][tx * 8];
            float4 b1 = *(const float4*)&Bs[k][tx * 8 + 4];
            float aR[4] = {a0.x, a0.y, a0.z, a0.w};
            float bR[8] = {b0.x, b0.y, b0.z, b0.w, b1.x, b1.y, b1.z, b1.w};
            #pragma unroll
            for (int i = 0; i < 4; i++)
                #pragma unroll
                for (int j = 0; j < 8; j++)
                    acc[i][j] += aR[i] * bR[j];
        }
        __syncthreads();
    }

    // bias + tanh into v
    float bloc[8];
    #pragma unroll
    for (int j = 0; j < 8; j++) bloc[j] = g_bc[tx * 8 + j];
    float v[4][8];
    #pragma unroll
    for (int i = 0; i < 4; i++)
        #pragma unroll
        for (int j = 0; j < 8; j++) v[i][j] = tanhf(acc[i][j] + bloc[j]);

    // epilogue: 8 phases of 8 rows over aliased smem
    float (*abs8)[128] = (float(*)[128])smem_main;  // 4 KB <= 6 KB
    int w = tid >> 5, lane = tid & 31;
    #pragma unroll 1
    for (int ph = 0; ph < 8; ph++) {
        if ((ty >> 1) == ph) {
            int lr = (ty & 1) * 4;
            #pragma unroll
            for (int i = 0; i < 4; i++)
                #pragma unroll
                for (int j = 0; j < 8; j++)
                    abs8[lr + i][tx * 8 + j] = v[i][j];
        }
        __syncthreads();
        int grow = m0 + ph * 8 + w;  // one row per warp
        float areg[4];
        #pragma unroll
        for (int j = 0; j < 4; j++) areg[j] = abs8[w][j * 32 + lane];
        float a2 = bs_s[lane];
        #pragma unroll
        for (int j = 0; j < 4; j++)
            #pragma unroll
            for (int d = 0; d < 32; d++) {
                float a = __shfl_sync(0xffffffffu, areg[j], d);
                a2 += a * Ws[(j * 32 + d) * KC + lane];
            }
        float m = a2;
        #pragma unroll
        for (int o = 16; o > 0; o >>= 1) m = fmaxf(m, __shfl_xor_sync(0xffffffffu, m, o));
        float e = expf(a2 - m);
        float s = e;
        #pragma unroll
        for (int o = 16; o > 0; o >>= 1) s += __shfl_xor_sync(0xffffffffu, s, o);
        if (grow < NN) g_S[(size_t)grow * KC + lane] = e / s;
        __syncthreads();
    }
}

// ---------------- V[c] = S[c] - dinv2[c]*sum_{r in in(c)} dinv2[r]*S[r] ----------------
__global__ __launch_bounds__(256) void k_lapV() {
    int tid = blockIdx.x * blockDim.x + threadIdx.x;
    int lane = tid & 31;
    int i = tid >> 5;
    if (i >= NN) return;
    float sv = g_S[(size_t)i * KC + lane];
    float di = g_dinv2[i];
    float u = 0.f;
    int s0 = i ? g_off_in[i - 1] : 0;
    int s1 = g_off_in[i];
    for (int idx = s0; idx < s1; idx++) {
        int r = g_src_in[idx];
        u += g_dinv2[r] * g_S[(size_t)r * KC + lane];
    }
    g_V[(size_t)i * KC + lane] = sv - di * u;
}

// ---------------- adj[a][b] = sum_i V[i,a] * S[i,b] ----------------
__global__ __launch_bounds__(256) void k_adj() {
    __shared__ float sh[8][KC * KC];
    int tid = threadIdx.x, lane = tid & 31, w = tid >> 5;
    float acc[32];
    #pragma unroll
    for (int a = 0; a < 32; a++) acc[a] = 0.f;
    int gw = blockIdx.x * 8 + w, tw = gridDim.x * 8;
    for (int i = gw; i < NN; i += tw) {
        float vv = g_V[(size_t)i * 32 + lane];
        float sv = g_S[(size_t)i * 32 + lane];
        #pragma unroll
        for (int a = 0; a < 32; a++) {
            float va = __shfl_sync(0xffffffffu, vv, a);
            acc[a] += va * sv;
        }
    }
    #pragma unroll
    for (int a = 0; a < 32; a++) sh[w][a * 32 + lane] = acc[a];
    __syncthreads();
    for (int j = tid; j < KC * KC; j += blockDim.x) {
        float s = 0.f;
        #pragma unroll
        for (int w2 = 0; w2 < 8; w2++) s += sh[w2][j];
        atomicAdd(&G_ADJ(j), s);
    }
}

// ---------------- finalize: emb = (cs@W1 + NN*b1)/32 ; pos_penalty ----------------
__global__ void k_final(const float* __restrict__ W1, const float* __restrict__ b1,
                        float* __restrict__ out, int out_size) {
    int t = threadIdx.x; // 256 = D1
    float acc = (float)NN * b1[t];
    for (int f = 0; f < FIN; f++) acc += G_CS(f) * W1[(size_t)f * D1 + t];
    if (t < out_size) out[t] = acc * (1.f / 32.f);
    if (t < 32) {
        float rs = 0.f;
        #pragma unroll
        for (int b = 0; b < 32; b++) rs += fabsf(G_ADJ(t * 32 + b));
        float d = G_ADJ(t * 33) / fmaxf(rs, 1e-12f);
        float contrib = (d - 1.f) * (d - 1.f) + 31.f * d * d;
        #pragma unroll
        for (int o = 16; o > 0; o >>= 1) contrib += __shfl_xor_sync(0xffffffffu, contrib, o);
        if (t == 0 && out_size > D1) out[D1] = contrib * (1.f / 1024.f);
    }
}

// ---------------- launch ----------------
extern "C" void kernel_launch(void* const* d_in, const int* in_sizes, int n_in,
                              void* d_out, int out_size) {
    const float* feat  = (const float*)d_in[0];
    const int*   edges = (const int*)d_in[1];   // (2, E) int32
    const float* W1    = (const float*)d_in[2];
    const float* b1    = (const float*)d_in[3];
    const float* fc1W  = (const float*)d_in[4];
    const float* fc1b  = (const float*)d_in[5];
    const float* fc2W  = (const float*)d_in[6];
    const float* fc2b  = (const float*)d_in[7];
    float* out = (float*)d_out;

    void *p_deg = nullptr, *p_small = nullptr;
    cudaGetSymbolAddress(&p_deg, g_deg);
    cudaGetSymbolAddress(&p_small, g_small);
    cudaMemsetAsync(p_deg, 0, sizeof(int) * 2 * NN);
    cudaMemsetAsync(p_small, 0, sizeof(float) * (KC * KC + FIN));

    k_degree<<<1024, 256>>>(edges);
    k_scan2<<<2, 1024>>>();
    k_fill<<<1024, 256>>>(edges);
    k_agg<<<(NN + 7) / 8, 256>>>(feat);        // kernel launch index 3 -> profiled
    k_wcbc<<<9, 128>>>(W1, fc1W, b1, fc1b);
    k_gemm_fused<<<(NN + 63) / 64, 256>>>(fc2W, fc2b);
    k_lapV<<<(NN * 32 + 255) / 256, 256>>>();
    k_adj<<<148, 256>>>();
    k_final<<<1, 256>>>(W1, b1, out, out_size);
}